// round 16
// baseline (speedup 1.0000x reference)
#include <cuda_runtime.h>
#include <mma.h>
#include <math.h>

using namespace nvcuda;

#define THREADS 512
#define NGRAPH  512

// ---------------- smem layout (float offsets) ----------------
#define F_A0    0          // 14336 : Adj(ld104) -> agg_hi/D2/h1_hi (ld112) -> Adj again
#define F_A1    14336      // 14336 : agg_lo / h1_lo (ld112)
#define F_B0    28672      // 11648 : feat_hi -> W1_hi
#define F_B1    40320      // 11648 : feat_lo -> W1_lo
#define F_W2H   28672      //  3328 : phase C: W2_hi (col-major ld104)
#define F_W2L   32000      //  3328 : W2_lo
#define F_ZH    35328      //  4096 : z_hi (row-major ld32, 128 rows)
#define F_ZL    39424      //  4096 : z_lo
#define F_B1S   51968      //   112 : b1 padded
#define F_B2S   52080      //    32 : b2 padded
#define F_SC    52112      //   128 : epilogue scratch
#define F_D4    52240      //  4096 : D3/D4 fp32 stage (ld32)
#define SMEM_FLOATS 56336
#define SMEM_BYTES  (SMEM_FLOATS * 4)

typedef wmma::fragment<wmma::matrix_a, 16, 16, 8, wmma::precision::tf32, wmma::row_major> FragA;
typedef wmma::fragment<wmma::matrix_b, 16, 16, 8, wmma::precision::tf32, wmma::row_major> FragBR;
typedef wmma::fragment<wmma::matrix_b, 16, 16, 8, wmma::precision::tf32, wmma::col_major> FragBC;
typedef wmma::fragment<wmma::accumulator, 16, 16, 8, float> FragC;

static __device__ __forceinline__ float tf32_rn(float x) {
    float r; asm("cvt.rna.tf32.f32 %0, %1;" : "=f"(r) : "f"(x)); return r;
}
static __device__ __forceinline__ void split_hl(float v, float& h, float& l) {
    h = __uint_as_float(__float_as_uint(v) & 0xFFFFE000u);   // exact tf32 (RZ truncation)
    l = tf32_rn(v - h);                                      // residual, rounded to tf32
}

__global__ void __launch_bounds__(THREADS, 1) net_kernel(
    const float* __restrict__ feat, const int* __restrict__ esrc,
    const float* __restrict__ self_feat, const float* __restrict__ x3d,
    const float* __restrict__ W1, const float* __restrict__ b1,
    const float* __restrict__ W2, const float* __restrict__ b2,
    const float* __restrict__ Wv2, const float* __restrict__ Wo2,
    const float* __restrict__ g2, const float* __restrict__ be2,
    const float* __restrict__ Wv3, const float* __restrict__ Wo3,
    const float* __restrict__ g3, const float* __restrict__ be3,
    const float* __restrict__ Wf1, const float* __restrict__ bf1,
    const float* __restrict__ Wf2, const float* __restrict__ bf2,
    float* __restrict__ out)
{
    extern __shared__ float smf[];
    const int g    = blockIdx.x;
    const int tid  = threadIdx.x;
    const int lane = tid & 31;
    const int warp = tid >> 5;
    const int mw   = warp >> 1;       // M-tile (0..7), rows 16*mw..16*mw+15
    const int nh   = warp & 1;        // N-half
    const int m0   = mw * 16;

    // ---------------- P0: zero Adj, stage Adj/feat/biases ----------------
    {
        float4* a4 = (float4*)(smf + F_A0);
        for (int i = tid; i < 3328; i += THREADS) a4[i] = make_float4(0.f, 0.f, 0.f, 0.f);
    }
    __syncthreads();
    if (tid < 100) {           // Adj[m][s] += 1/16 (row-owned: no races, handles dup edges)
        const int* ep = esrc + (size_t)g * 1600 + tid * 16;
        float* row = smf + F_A0 + tid * 104;
        #pragma unroll
        for (int j = 0; j < 16; j++) row[ep[j] - g * 100] += 0.0625f;
    }
    for (int e = tid; e < 11648; e += THREADS) {    // feat hi/lo: [s:104][d:112]
        int s = e / 112, d = e % 112;
        float v = (s < 100 && d < 100) ? feat[(size_t)g * 10000 + s * 100 + d] : 0.f;
        float h, l; split_hl(v, h, l);
        smf[F_B0 + e] = h; smf[F_B1 + e] = l;
    }
    if (tid < 112) smf[F_B1S + tid] = (tid < 100) ? b1[tid] : 0.f;
    if (tid < 32)  smf[F_B2S + tid] = (tid < 20)  ? b2[tid] : 0.f;
    __syncthreads();

    const int ntw   = nh ? 3 : 4;       // N-tiles this warp (GEMM A/B, N=112)
    const int nbase = nh ? 64 : 0;

    // ---------------- P1: GEMM A  agg = Adj @ feat  (2 passes) ----------------
    {
        FragA a[13];
        #pragma unroll
        for (int k = 0; k < 13; k++)
            wmma::load_matrix_sync(a[k], smf + F_A0 + m0 * 104 + k * 8, 104);
        FragC c[4];
        #pragma unroll
        for (int t = 0; t < 4; t++) wmma::fill_fragment(c[t], 0.f);

        #pragma unroll
        for (int pass = 0; pass < 2; pass++) {
            const float* bb = smf + (pass ? F_B1 : F_B0);
            #pragma unroll
            for (int k = 0; k < 13; k++) {
                #pragma unroll
                for (int t = 0; t < 4; t++) {
                    if (t < ntw) {
                        FragBR b;
                        wmma::load_matrix_sync(b, bb + k * 8 * 112 + nbase + t * 16, 112);
                        wmma::mma_sync(c[t], a[k], b, c[t]);
                    }
                }
            }
        }
        __syncthreads();   // all mma done: Adj & feat now dead
        #pragma unroll
        for (int t = 0; t < 4; t++)
            if (t < ntw)
                wmma::store_matrix_sync(smf + F_A0 + m0 * 112 + nbase + t * 16, c[t], 112, wmma::mem_row_major);
    }
    // stage W1 hi/lo (overwrites feat): buffer index == o*104+d
    for (int e = tid; e < 11648; e += THREADS) {
        int o = e / 104, d = e % 104;
        float v = (o < 100 && d < 100) ? W1[o * 100 + d] : 0.f;
        float h, l; split_hl(v, h, l);
        smf[F_B0 + e] = h; smf[F_B1 + e] = l;
    }
    __syncthreads();
    // split agg in place: hi @F_A0, lo @F_A1
    for (int e = tid; e < 14336; e += THREADS) {
        float h, l; split_hl(smf[F_A0 + e], h, l);
        smf[F_A0 + e] = h; smf[F_A1 + e] = l;
    }
    __syncthreads();

    // ---------------- P2: GEMM B  D2 = agg @ W1^T  (3 passes: hh, hl, lh) ----------------
    {
        FragA a[13];
        #pragma unroll
        for (int k = 0; k < 13; k++)
            wmma::load_matrix_sync(a[k], smf + F_A0 + m0 * 112 + k * 8, 112);
        FragC c[4];
        #pragma unroll
        for (int t = 0; t < 4; t++) wmma::fill_fragment(c[t], 0.f);

        #pragma unroll
        for (int pass = 0; pass < 2; pass++) {     // hh, hl
            const float* bb = smf + (pass ? F_B1 : F_B0);
            #pragma unroll
            for (int k = 0; k < 13; k++) {
                #pragma unroll
                for (int t = 0; t < 4; t++) {
                    if (t < ntw) {
                        FragBC b;
                        wmma::load_matrix_sync(b, bb + (nbase + t * 16) * 104 + k * 8, 104);
                        wmma::mma_sync(c[t], a[k], b, c[t]);
                    }
                }
            }
        }
        #pragma unroll
        for (int k = 0; k < 13; k++)               // reload A = agg_lo
            wmma::load_matrix_sync(a[k], smf + F_A1 + m0 * 112 + k * 8, 112);
        #pragma unroll
        for (int k = 0; k < 13; k++) {             // lh
            #pragma unroll
            for (int t = 0; t < 4; t++) {
                if (t < ntw) {
                    FragBC b;
                    wmma::load_matrix_sync(b, smf + F_B0 + (nbase + t * 16) * 104 + k * 8, 104);
                    wmma::mma_sync(c[t], a[k], b, c[t]);
                }
            }
        }
        __syncthreads();   // agg & W1 dead
        #pragma unroll
        for (int t = 0; t < 4; t++)
            if (t < ntw)
                wmma::store_matrix_sync(smf + F_A0 + m0 * 112 + nbase + t * 16, c[t], 112, wmma::mem_row_major);
    }
    // stage W2 hi/lo (col-major, overwrites W1_hi head): buffer index == c*104+o
    for (int e = tid; e < 3328; e += THREADS) {
        int cc = e / 104, o = e % 104;
        float v = (cc < 20 && o < 100) ? W2[cc * 100 + o] : 0.f;
        float h, l; split_hl(v, h, l);
        smf[F_W2H + e] = h; smf[F_W2L + e] = l;
    }
    __syncthreads();
    // h1 = relu(D2 + b1), split in place
    for (int e = tid; e < 14336; e += THREADS) {
        float v = fmaxf(smf[F_A0 + e] + smf[F_B1S + (e % 112)], 0.f);
        float h, l; split_hl(v, h, l);
        smf[F_A0 + e] = h; smf[F_A1 + e] = l;
    }
    __syncthreads();

    // ---------------- P3: GEMM C  D3 = h1 @ W2^T  (3 passes, N=32) ----------------
    {
        FragA a[13];
        #pragma unroll
        for (int k = 0; k < 13; k++)
            wmma::load_matrix_sync(a[k], smf + F_A0 + m0 * 112 + k * 8, 112);
        FragC cz;
        wmma::fill_fragment(cz, 0.f);
        const int n0 = nh * 16;

        #pragma unroll
        for (int pass = 0; pass < 2; pass++) {     // hh, hl
            const float* bb = smf + (pass ? F_W2L : F_W2H);
            #pragma unroll
            for (int k = 0; k < 13; k++) {
                FragBC b;
                wmma::load_matrix_sync(b, bb + n0 * 104 + k * 8, 104);
                wmma::mma_sync(cz, a[k], b, cz);
            }
        }
        #pragma unroll
        for (int k = 0; k < 13; k++)
            wmma::load_matrix_sync(a[k], smf + F_A1 + m0 * 112 + k * 8, 112);
        #pragma unroll
        for (int k = 0; k < 13; k++) {             // lh
            FragBC b;
            wmma::load_matrix_sync(b, smf + F_W2H + n0 * 104 + k * 8, 104);
            wmma::mma_sync(cz, a[k], b, cz);
        }
        __syncthreads();   // h1 dead
        wmma::store_matrix_sync(smf + F_D4 + m0 * 32 + n0, cz, 32, wmma::mem_row_major);
    }
    // zero Adj region for rebuild
    {
        float4* a4 = (float4*)(smf + F_A0);
        for (int i = tid; i < 3328; i += THREADS) a4[i] = make_float4(0.f, 0.f, 0.f, 0.f);
    }
    __syncthreads();
    // split z (force pad rows >=100 to zero) + rebuild Adj
    for (int e = tid; e < 4096; e += THREADS) {
        int s = e >> 5;
        float v = (s < 100) ? smf[F_D4 + e] : 0.f;
        float h, l; split_hl(v, h, l);
        smf[F_ZH + e] = h; smf[F_ZL + e] = l;
    }
    if (tid < 100) {
        const int* ep = esrc + (size_t)g * 1600 + tid * 16;
        float* row = smf + F_A0 + tid * 104;
        #pragma unroll
        for (int j = 0; j < 16; j++) row[ep[j] - g * 100] += 0.0625f;
    }
    __syncthreads();

    // ---------------- P4: GEMM D  D4 = Adj @ z  (2 passes, N=32) ----------------
    {
        FragA a[13];
        #pragma unroll
        for (int k = 0; k < 13; k++)
            wmma::load_matrix_sync(a[k], smf + F_A0 + m0 * 104 + k * 8, 104);
        FragC cz;
        wmma::fill_fragment(cz, 0.f);
        const int n0 = nh * 16;
        #pragma unroll
        for (int pass = 0; pass < 2; pass++) {
            const float* bb = smf + (pass ? F_ZL : F_ZH);
            #pragma unroll
            for (int k = 0; k < 13; k++) {
                FragBR b;
                wmma::load_matrix_sync(b, bb + k * 8 * 32 + n0, 32);
                wmma::mma_sync(cz, a[k], b, cz);
            }
        }
        wmma::store_matrix_sync(smf + F_D4 + m0 * 32 + n0, cz, 32, wmma::mem_row_major);
    }
    __syncthreads();

    // ---------------- P5 (warp 0): pool + attn2 + attn3 + MLP ----------------
    if (warp == 0) {
        float* sc = smf + F_SC;
        if (lane < 20) {
            const float bb = smf[F_B2S + lane];
            float s = 0.f;
            #pragma unroll 10
            for (int n = 0; n < 100; n++)
                s += fmaxf(smf[F_D4 + n * 32 + lane] + bb, 0.f);
            sc[64 + lane] = s * 0.01f;
        }
        __syncwarp();

        // cross-attn 2 (len-1 softmax == identity): Z = Wo2 @ (Wv2 @ sf)
        {
            float v = 0.f;
            const float4* wv = (const float4*)(Wv2 + lane * 200);
            const float4* xf = (const float4*)(self_feat + (size_t)g * 200);
            #pragma unroll
            for (int j = 0; j < 50; j++) {
                float4 a = wv[j], c = xf[j];
                v = fmaf(a.x, c.x, fmaf(a.y, c.y, fmaf(a.z, c.z, fmaf(a.w, c.w, v))));
            }
            sc[lane] = v;
        }
        __syncwarp();
        float y2 = 0.f;
        if (lane < 20) {
            float z = 0.f;
            #pragma unroll
            for (int l = 0; l < 32; l++) z = fmaf(Wo2[lane * 32 + l], sc[l], z);
            y2 = sc[64 + lane] + z;
            sc[32 + lane] = y2;
        }
        __syncwarp();
        if (lane == 0) {
            float mu = 0.f;
            #pragma unroll
            for (int o = 0; o < 20; o++) mu += sc[32 + o];
            mu *= 0.05f;
            float var = 0.f;
            #pragma unroll
            for (int o = 0; o < 20; o++) { float d = sc[32 + o] - mu; var = fmaf(d, d, var); }
            var *= 0.05f;
            sc[100] = mu;
            sc[101] = 1.f / sqrtf(var + 1e-5f);
        }
        __syncwarp();
        if (lane < 20)
            sc[64 + lane] = (y2 - sc[100]) * sc[101] * g2[lane] + be2[lane];
        __syncwarp();

        // cross-attn 3
        {
            float v = 0.f;
            const float4* wv = (const float4*)(Wv3 + lane * 100);
            const float4* xf = (const float4*)(x3d + (size_t)g * 100);
            #pragma unroll
            for (int j = 0; j < 25; j++) {
                float4 a = wv[j], c = xf[j];
                v = fmaf(a.x, c.x, fmaf(a.y, c.y, fmaf(a.z, c.z, fmaf(a.w, c.w, v))));
            }
            sc[lane] = v;
        }
        __syncwarp();
        float y3 = 0.f;
        if (lane < 20) {
            float z = 0.f;
            #pragma unroll
            for (int l = 0; l < 32; l++) z = fmaf(Wo3[lane * 32 + l], sc[l], z);
            y3 = sc[64 + lane] + z;
            sc[32 + lane] = y3;
        }
        __syncwarp();
        if (lane == 0) {
            float mu = 0.f;
            #pragma unroll
            for (int o = 0; o < 20; o++) mu += sc[32 + o];
            mu *= 0.05f;
            float var = 0.f;
            #pragma unroll
            for (int o = 0; o < 20; o++) { float d = sc[32 + o] - mu; var = fmaf(d, d, var); }
            var *= 0.05f;
            sc[100] = mu;
            sc[101] = 1.f / sqrtf(var + 1e-5f);
        }
        __syncwarp();
        if (lane < 20)
            sc[64 + lane] = (y3 - sc[100]) * sc[101] * g3[lane] + be3[lane];
        __syncwarp();

        // MLP head
        if (lane < 10) {
            float f = bf1[lane];
            #pragma unroll
            for (int o = 0; o < 20; o++) f = fmaf(Wf1[lane * 20 + o], sc[64 + o], f);
            sc[84 + lane] = fmaxf(f, 0.f);
        }
        __syncwarp();
        if (lane == 0) {
            float r = bf2[0];
            #pragma unroll
            for (int k = 0; k < 10; k++) r = fmaf(Wf2[k], sc[84 + k], r);
            out[g] = r;
        }
    }
}

extern "C" void kernel_launch(void* const* d_in, const int* in_sizes, int n_in,
                              void* d_out, int out_size)
{
    const float* feat      = (const float*)d_in[0];
    const int*   esrc      = (const int*)  d_in[1];
    const float* self_feat = (const float*)d_in[3];
    const float* x3d       = (const float*)d_in[4];
    const float* W1  = (const float*)d_in[5];
    const float* b1  = (const float*)d_in[6];
    const float* W2  = (const float*)d_in[7];
    const float* b2  = (const float*)d_in[8];
    const float* Wv2 = (const float*)d_in[11];
    const float* Wo2 = (const float*)d_in[12];
    const float* g2  = (const float*)d_in[13];
    const float* be2 = (const float*)d_in[14];
    const float* Wv3 = (const float*)d_in[17];
    const float* Wo3 = (const float*)d_in[18];
    const float* g3  = (const float*)d_in[19];
    const float* be3 = (const float*)d_in[20];
    const float* Wf1 = (const float*)d_in[21];
    const float* bf1 = (const float*)d_in[22];
    const float* Wf2 = (const float*)d_in[23];
    const float* bf2 = (const float*)d_in[24];
    float* out = (float*)d_out;

    cudaFuncSetAttribute(net_kernel, cudaFuncAttributeMaxDynamicSharedMemorySize, SMEM_BYTES);
    net_kernel<<<NGRAPH, THREADS, SMEM_BYTES>>>(
        feat, esrc, self_feat, x3d,
        W1, b1, W2, b2,
        Wv2, Wo2, g2, be2,
        Wv3, Wo3, g3, be3,
        Wf1, bf1, Wf2, bf2, out);
}

// round 17
// speedup vs baseline: 1.6693x; 1.6693x over previous
#include <cuda_runtime.h>
#include <cuda_bf16.h>
#include <mma.h>
#include <math.h>

using namespace nvcuda;

#define THREADS 512
#define NGRAPH  512

// ---------------- smem layout (byte offsets) ----------------
#define O_ADJ   0u         // bf16 [128][112]  = 28672
#define O_AH    28672u     // bf16 [128][112]  agg_hi / h1_hi
#define O_AL    57344u     // bf16 [128][112]  agg_lo / h1_lo
#define O_BH    86016u     // bf16 [112][112]  feat_hi -> W1T_hi = 25088
#define O_BL    111104u    // bf16 [112][112]  feat_lo -> W1T_lo
#define O_R0    136192u    // f32  [128][112]  C staging = 57344
#define O_W2H   193536u    // bf16 [112][32]   W2T_hi = 7168
#define O_W2L   200704u    // bf16 [112][32]   W2T_lo
#define O_ZH    207872u    // bf16 [112][32]   z_hi
#define O_ZL    215040u    // bf16 [112][32]   z_lo
#define O_B1S   222208u    // f32 112
#define O_B2S   222656u    // f32 32
#define O_SC    222784u    // f32 128
#define SMEM_BYTES 223296u

typedef wmma::fragment<wmma::matrix_a, 16, 16, 16, __nv_bfloat16, wmma::row_major> FragA;
typedef wmma::fragment<wmma::matrix_b, 16, 16, 16, __nv_bfloat16, wmma::row_major> FragB;
typedef wmma::fragment<wmma::accumulator, 16, 16, 16, float> FragC;

static __device__ __forceinline__ void split_bf(float v, __nv_bfloat16& h, __nv_bfloat16& l) {
    h = __float2bfloat16_rn(v);
    l = __float2bfloat16_rn(v - __bfloat162float(h));
}

__global__ void __launch_bounds__(THREADS, 1) net_kernel(
    const float* __restrict__ feat, const int* __restrict__ esrc,
    const float* __restrict__ self_feat, const float* __restrict__ x3d,
    const float* __restrict__ W1, const float* __restrict__ b1,
    const float* __restrict__ W2, const float* __restrict__ b2,
    const float* __restrict__ Wv2, const float* __restrict__ Wo2,
    const float* __restrict__ g2, const float* __restrict__ be2,
    const float* __restrict__ Wv3, const float* __restrict__ Wo3,
    const float* __restrict__ g3, const float* __restrict__ be3,
    const float* __restrict__ Wf1, const float* __restrict__ bf1,
    const float* __restrict__ Wf2, const float* __restrict__ bf2,
    float* __restrict__ out)
{
    extern __shared__ char smc[];
    __nv_bfloat16* ADJ = (__nv_bfloat16*)(smc + O_ADJ);
    __nv_bfloat16* AH  = (__nv_bfloat16*)(smc + O_AH);
    __nv_bfloat16* AL  = (__nv_bfloat16*)(smc + O_AL);
    __nv_bfloat16* BH  = (__nv_bfloat16*)(smc + O_BH);
    __nv_bfloat16* BL  = (__nv_bfloat16*)(smc + O_BL);
    float*         R0  = (float*)        (smc + O_R0);
    __nv_bfloat16* W2H = (__nv_bfloat16*)(smc + O_W2H);
    __nv_bfloat16* W2L = (__nv_bfloat16*)(smc + O_W2L);
    __nv_bfloat16* ZH  = (__nv_bfloat16*)(smc + O_ZH);
    __nv_bfloat16* ZL  = (__nv_bfloat16*)(smc + O_ZL);
    float*         b1s = (float*)(smc + O_B1S);
    float*         b2s = (float*)(smc + O_B2S);
    float*         sc  = (float*)(smc + O_SC);

    const int g    = blockIdx.x;
    const int tid  = threadIdx.x;
    const int lane = tid & 31;
    const int warp = tid >> 5;
    const int mw   = warp >> 1;        // M tile 0..7
    const int nh   = warp & 1;         // N half
    const int m0   = mw * 16;
    const int ntw   = nh ? 3 : 4;      // N tiles for 112-wide GEMMs
    const int nbase = nh ? 64 : 0;

    // ---------------- P0: zero ADJ, build Adj, stage feat hi/lo, biases ----------------
    {
        uint4* z4 = (uint4*)ADJ;       // 28672 B = 1792 uint4
        for (int i = tid; i < 1792; i += THREADS) z4[i] = make_uint4(0u,0u,0u,0u);
    }
    __syncthreads();
    if (tid < 100) {                   // Adj[m][s] = count/16 (row-owned; exact in bf16)
        const int* ep = esrc + (size_t)g * 1600 + tid * 16;
        __nv_bfloat16* row = ADJ + tid * 112;
        #pragma unroll
        for (int j = 0; j < 16; j++) {
            int s = ep[j] - g * 100;
            row[s] = __float2bfloat16_rn(__bfloat162float(row[s]) + 0.0625f);
        }
    }
    for (int e = tid; e < 12544; e += THREADS) {   // feat [s:112][d:112]
        int s = e / 112, d = e % 112;
        float v = (s < 100 && d < 100) ? feat[(size_t)g * 10000 + s * 100 + d] : 0.f;
        __nv_bfloat16 h, l; split_bf(v, h, l);
        BH[e] = h; BL[e] = l;
    }
    if (tid < 112) b1s[tid] = (tid < 100) ? b1[tid] : 0.f;
    if (tid < 32)  b2s[tid] = (tid < 20)  ? b2[tid] : 0.f;
    __syncthreads();

    // ---------------- P1: agg = Adj @ feat  (2 passes: feat hi, feat lo) ----------------
    {
        FragA a[7];
        #pragma unroll
        for (int k = 0; k < 7; k++)
            wmma::load_matrix_sync(a[k], ADJ + m0 * 112 + k * 16, 112);
        FragC c[4];
        #pragma unroll
        for (int t = 0; t < 4; t++) wmma::fill_fragment(c[t], 0.f);
        #pragma unroll
        for (int pass = 0; pass < 2; pass++) {
            const __nv_bfloat16* bb = pass ? BL : BH;
            #pragma unroll
            for (int k = 0; k < 7; k++) {
                #pragma unroll
                for (int t = 0; t < 4; t++) {
                    if (t < ntw) {
                        FragB b;
                        wmma::load_matrix_sync(b, bb + k * 16 * 112 + nbase + t * 16, 112);
                        wmma::mma_sync(c[t], a[k], b, c[t]);
                    }
                }
            }
        }
        #pragma unroll
        for (int t = 0; t < 4; t++)
            if (t < ntw)
                wmma::store_matrix_sync(R0 + m0 * 112 + nbase + t * 16, c[t], 112, wmma::mem_row_major);
    }
    __syncthreads();

    // ---------------- stage W1T into BH/BL (feat dead), split agg R0 -> AH/AL ----------------
    {
        uint4* z0 = (uint4*)BH; uint4* z1 = (uint4*)BL;   // 25088 B = 1568 uint4
        for (int i = tid; i < 1568; i += THREADS) { z0[i] = make_uint4(0u,0u,0u,0u); z1[i] = make_uint4(0u,0u,0u,0u); }
    }
    __syncthreads();
    for (int e = tid; e < 10000; e += THREADS) {   // W1 [o][d] coalesced read -> BH[d*112+o]
        int o = e / 100, d = e % 100;
        __nv_bfloat16 h, l; split_bf(W1[e], h, l);
        BH[d * 112 + o] = h; BL[d * 112 + o] = l;
    }
    for (int e = tid; e < 14336; e += THREADS) {   // split agg
        __nv_bfloat16 h, l; split_bf(R0[e], h, l);
        AH[e] = h; AL[e] = l;
    }
    __syncthreads();

    // ---------------- P2: D2 = agg @ W1T  (3 passes: hh, hl, lh) ----------------
    {
        FragA a[7];
        #pragma unroll
        for (int k = 0; k < 7; k++)
            wmma::load_matrix_sync(a[k], AH + m0 * 112 + k * 16, 112);
        FragC c[4];
        #pragma unroll
        for (int t = 0; t < 4; t++) wmma::fill_fragment(c[t], 0.f);
        #pragma unroll
        for (int pass = 0; pass < 2; pass++) {     // hh, hl
            const __nv_bfloat16* bb = pass ? BL : BH;
            #pragma unroll
            for (int k = 0; k < 7; k++) {
                #pragma unroll
                for (int t = 0; t < 4; t++) {
                    if (t < ntw) {
                        FragB b;
                        wmma::load_matrix_sync(b, bb + k * 16 * 112 + nbase + t * 16, 112);
                        wmma::mma_sync(c[t], a[k], b, c[t]);
                    }
                }
            }
        }
        #pragma unroll
        for (int k = 0; k < 7; k++)                // A = agg_lo
            wmma::load_matrix_sync(a[k], AL + m0 * 112 + k * 16, 112);
        #pragma unroll
        for (int k = 0; k < 7; k++) {              // lh
            #pragma unroll
            for (int t = 0; t < 4; t++) {
                if (t < ntw) {
                    FragB b;
                    wmma::load_matrix_sync(b, BH + k * 16 * 112 + nbase + t * 16, 112);
                    wmma::mma_sync(c[t], a[k], b, c[t]);
                }
            }
        }
        __syncthreads();   // all reads of R0 (none) fine; ensure split consumers done - agg split already consumed
        #pragma unroll
        for (int t = 0; t < 4; t++)
            if (t < ntw)
                wmma::store_matrix_sync(R0 + m0 * 112 + nbase + t * 16, c[t], 112, wmma::mem_row_major);
    }
    __syncthreads();

    // ---------------- stage W2T, h1 = relu(D2+b1) split -> AH/AL ----------------
    {
        uint4* z0 = (uint4*)W2H; uint4* z1 = (uint4*)W2L;  // 7168 B = 448 uint4
        for (int i = tid; i < 448; i += THREADS) { z0[i] = make_uint4(0u,0u,0u,0u); z1[i] = make_uint4(0u,0u,0u,0u); }
    }
    __syncthreads();
    for (int e = tid; e < 2000; e += THREADS) {    // W2 [c][o] coalesced -> W2H[o*32+c]
        int c = e / 100, o = e % 100;
        __nv_bfloat16 h, l; split_bf(W2[e], h, l);
        W2H[o * 32 + c] = h; W2L[o * 32 + c] = l;
    }
    for (int e = tid; e < 14336; e += THREADS) {
        float v = fmaxf(R0[e] + b1s[e % 112], 0.f);
        __nv_bfloat16 h, l; split_bf(v, h, l);
        AH[e] = h; AL[e] = l;
    }
    __syncthreads();

    // ---------------- P3: D3 = h1 @ W2T (3 passes, N=32) ----------------
    {
        const int n0 = nh * 16;
        FragA a[7];
        #pragma unroll
        for (int k = 0; k < 7; k++)
            wmma::load_matrix_sync(a[k], AH + m0 * 112 + k * 16, 112);
        FragC cz;
        wmma::fill_fragment(cz, 0.f);
        #pragma unroll
        for (int pass = 0; pass < 2; pass++) {     // hh, hl
            const __nv_bfloat16* bb = pass ? W2L : W2H;
            #pragma unroll
            for (int k = 0; k < 7; k++) {
                FragB b;
                wmma::load_matrix_sync(b, bb + k * 16 * 32 + n0, 32);
                wmma::mma_sync(cz, a[k], b, cz);
            }
        }
        #pragma unroll
        for (int k = 0; k < 7; k++)
            wmma::load_matrix_sync(a[k], AL + m0 * 112 + k * 16, 112);
        #pragma unroll
        for (int k = 0; k < 7; k++) {              // lh
            FragB b;
            wmma::load_matrix_sync(b, W2H + k * 16 * 32 + n0, 32);
            wmma::mma_sync(cz, a[k], b, cz);
        }
        wmma::store_matrix_sync(R0 + m0 * 32 + n0, cz, 32, wmma::mem_row_major);
    }
    __syncthreads();

    // ---------------- split z: R0 [s][c] ld32 -> ZH/ZL (pad rows zero) ----------------
    for (int e = tid; e < 3584; e += THREADS) {
        int s = e >> 5;
        float v = (s < 100) ? R0[e] : 0.f;
        __nv_bfloat16 h, l; split_bf(v, h, l);
        ZH[e] = h; ZL[e] = l;
    }
    __syncthreads();

    // ---------------- P4: D4 = Adj @ z (2 passes, N=32) ----------------
    {
        const int n0 = nh * 16;
        FragA a[7];
        #pragma unroll
        for (int k = 0; k < 7; k++)
            wmma::load_matrix_sync(a[k], ADJ + m0 * 112 + k * 16, 112);
        FragC cz;
        wmma::fill_fragment(cz, 0.f);
        #pragma unroll
        for (int pass = 0; pass < 2; pass++) {
            const __nv_bfloat16* bb = pass ? ZL : ZH;
            #pragma unroll
            for (int k = 0; k < 7; k++) {
                FragB b;
                wmma::load_matrix_sync(b, bb + k * 16 * 32 + n0, 32);
                wmma::mma_sync(cz, a[k], b, cz);
            }
        }
        wmma::store_matrix_sync(R0 + m0 * 32 + n0, cz, 32, wmma::mem_row_major);
    }
    __syncthreads();

    // ---------------- P5 (warp 0): pool + attn2 + attn3 + MLP ----------------
    if (warp == 0) {
        if (lane < 20) {
            const float bb = b2s[lane];
            float s = 0.f;
            #pragma unroll 10
            for (int n = 0; n < 100; n++)
                s += fmaxf(R0[n * 32 + lane] + bb, 0.f);
            sc[64 + lane] = s * 0.01f;
        }
        __syncwarp();

        // cross-attn 2 (len-1 softmax == identity): Z = Wo2 @ (Wv2 @ sf)
        {
            float v = 0.f;
            const float4* wv = (const float4*)(Wv2 + lane * 200);
            const float4* xf = (const float4*)(self_feat + (size_t)g * 200);
            #pragma unroll
            for (int j = 0; j < 50; j++) {
                float4 a = wv[j], c = xf[j];
                v = fmaf(a.x, c.x, fmaf(a.y, c.y, fmaf(a.z, c.z, fmaf(a.w, c.w, v))));
            }
            sc[lane] = v;
        }
        __syncwarp();
        float y2 = 0.f;
        if (lane < 20) {
            float z = 0.f;
            #pragma unroll
            for (int l = 0; l < 32; l++) z = fmaf(Wo2[lane * 32 + l], sc[l], z);
            y2 = sc[64 + lane] + z;
            sc[32 + lane] = y2;
        }
        __syncwarp();
        if (lane == 0) {
            float mu = 0.f;
            #pragma unroll
            for (int o = 0; o < 20; o++) mu += sc[32 + o];
            mu *= 0.05f;
            float var = 0.f;
            #pragma unroll
            for (int o = 0; o < 20; o++) { float d = sc[32 + o] - mu; var = fmaf(d, d, var); }
            var *= 0.05f;
            sc[100] = mu;
            sc[101] = 1.f / sqrtf(var + 1e-5f);
        }
        __syncwarp();
        if (lane < 20)
            sc[64 + lane] = (y2 - sc[100]) * sc[101] * g2[lane] + be2[lane];
        __syncwarp();

        // cross-attn 3
        {
            float v = 0.f;
            const float4* wv = (const float4*)(Wv3 + lane * 100);
            const float4* xf = (const float4*)(x3d + (size_t)g * 100);
            #pragma unroll
            for (int j = 0; j < 25; j++) {
                float4 a = wv[j], c = xf[j];
                v = fmaf(a.x, c.x, fmaf(a.y, c.y, fmaf(a.z, c.z, fmaf(a.w, c.w, v))));
            }
            sc[lane] = v;
        }
        __syncwarp();
        float y3 = 0.f;
        if (lane < 20) {
            float z = 0.f;
            #pragma unroll
            for (int l = 0; l < 32; l++) z = fmaf(Wo3[lane * 32 + l], sc[l], z);
            y3 = sc[64 + lane] + z;
            sc[32 + lane] = y3;
        }
        __syncwarp();
        if (lane == 0) {
            float mu = 0.f;
            #pragma unroll
            for (int o = 0; o < 20; o++) mu += sc[32 + o];
            mu *= 0.05f;
            float var = 0.f;
            #pragma unroll
            for (int o = 0; o < 20; o++) { float d = sc[32 + o] - mu; var = fmaf(d, d, var); }
            var *= 0.05f;
            sc[100] = mu;
            sc[101] = 1.f / sqrtf(var + 1e-5f);
        }
        __syncwarp();
        if (lane < 20)
            sc[64 + lane] = (y3 - sc[100]) * sc[101] * g3[lane] + be3[lane];
        __syncwarp();

        // MLP head
        if (lane < 10) {
            float f = bf1[lane];
            #pragma unroll
            for (int o = 0; o < 20; o++) f = fmaf(Wf1[lane * 20 + o], sc[64 + o], f);
            sc[84 + lane] = fmaxf(f, 0.f);
        }
        __syncwarp();
        if (lane == 0) {
            float r = bf2[0];
            #pragma unroll
            for (int k = 0; k < 10; k++) r = fmaf(Wf2[k], sc[84 + k], r);
            out[g] = r;
        }
    }
}

extern "C" void kernel_launch(void* const* d_in, const int* in_sizes, int n_in,
                              void* d_out, int out_size)
{
    const float* feat      = (const float*)d_in[0];
    const int*   esrc      = (const int*)  d_in[1];
    const float* self_feat = (const float*)d_in[3];
    const float* x3d       = (const float*)d_in[4];
    const float* W1  = (const float*)d_in[5];
    const float* b1  = (const float*)d_in[6];
    const float* W2  = (const float*)d_in[7];
    const float* b2  = (const float*)d_in[8];
    const float* Wv2 = (const float*)d_in[11];
    const float* Wo2 = (const float*)d_in[12];
    const float* g2  = (const float*)d_in[13];
    const float* be2 = (const float*)d_in[14];
    const float* Wv3 = (const float*)d_in[17];
    const float* Wo3 = (const float*)d_in[18];
    const float* g3  = (const float*)d_in[19];
    const float* be3 = (const float*)d_in[20];
    const float* Wf1 = (const float*)d_in[21];
    const float* bf1 = (const float*)d_in[22];
    const float* Wf2 = (const float*)d_in[23];
    const float* bf2 = (const float*)d_in[24];
    float* out = (float*)d_out;

    cudaFuncSetAttribute(net_kernel, cudaFuncAttributeMaxDynamicSharedMemorySize, SMEM_BYTES);
    net_kernel<<<NGRAPH, THREADS, SMEM_BYTES>>>(
        feat, esrc, self_feat, x3d,
        W1, b1, W2, b2,
        Wv2, Wo2, g2, be2,
        Wv3, Wo3, g3, be3,
        Wf1, bf1, Wf2, bf2, out);
}